// round 1
// baseline (speedup 1.0000x reference)
#include <cuda_runtime.h>

#define N_ 32
#define T_ 48

// ---------------- scratch (t-major: [T][N][C][H][W]) ----------------
__device__ float g_xt[(size_t)T_*N_*32*32];          // x transposed (C=1)
__device__ float g_h1[(size_t)T_*N_*16*28*28];       // conv1 spikes
__device__ float g_h2[(size_t)T_*N_*32*24*24];       // conv2 spikes
__device__ float g_p1[(size_t)T_*N_*32*12*12];       // pool1 spikes
__device__ float g_h3[(size_t)T_*N_*32*8*8];         // conv3 spikes
__device__ float g_p2[(size_t)T_*N_*32*4*4];         // pool2 spikes
__device__ float g_wt1[512*128];                     // Wf1 transposed [k][o]
__device__ float g_z1[(size_t)T_*N_*128];            // fc1 pre-activations

// ---------------- transpose x: [N,1,32,32,T] -> [T][N][32][32] ----------------
__global__ void k_transpose_x(const float* __restrict__ x) {
    int idx = blockIdx.x * blockDim.x + threadIdx.x;
    if (idx >= N_*32*32) return;
    int n = idx >> 10, hw = idx & 1023;
    const float* xp = x + (size_t)idx * T_;
    #pragma unroll
    for (int t = 0; t < T_; t++)
        g_xt[((size_t)t*N_ + n)*1024 + hw] = xp[t];
}

// ---------------- transpose Wf1: [128][512] -> [512][128] ----------------
__global__ void k_transpose_wf1(const float* __restrict__ Wf1) {
    int idx = blockIdx.x * blockDim.x + threadIdx.x;
    if (idx >= 128*512) return;
    int o = idx >> 9, k = idx & 511;
    g_wt1[k*128 + o] = Wf1[idx];
}

// ---------------- fused 5x5 VALID conv + LIF spike scan ----------------
// Thread owns GO output channels x WOT output columns; walks T in chunks of 4.
template<int CIN,int COUT,int HIN,int WIN,int GO,int WOT,int HOT>
__global__ void k_conv_spike(const float* __restrict__ in,
                             const float* __restrict__ Wc,
                             const float* __restrict__ bc,
                             float* __restrict__ out) {
    constexpr int HOUT = HIN-4, WOUT = WIN-4;
    constexpr int NWG  = WOUT/WOT;
    constexpr int NOG  = COUT/GO;
    constexpr int LANES = NWG*NOG;
    constexpr size_t TS_IN  = (size_t)N_*CIN*HIN*WIN;
    constexpr size_t TS_OUT = (size_t)N_*COUT*HOUT*WOUT;
    extern __shared__ float ws[];   // COUT*CIN*25 weights
    {
        int tid = threadIdx.y*LANES + threadIdx.x;
        for (int i = tid; i < COUT*CIN*25; i += LANES*HOT) ws[i] = Wc[i];
    }
    __syncthreads();

    int wg = threadIdx.x % NWG;
    int og = threadIdx.x / NWG;
    int wo = wg * WOT;
    int ho = blockIdx.x*HOT + threadIdx.y;
    int n  = blockIdx.y;

    float u[GO][WOT];
    float bb[GO];
    #pragma unroll
    for (int g = 0; g < GO; g++) {
        bb[g] = bc[og*GO + g];
        #pragma unroll
        for (int ww = 0; ww < WOT; ww++) u[g][ww] = 0.f;
    }

    const float* inb = in + (size_t)n*CIN*HIN*WIN + wo;
    float* outb = out + (size_t)n*COUT*HOUT*WOUT
                      + (size_t)og*GO*HOUT*WOUT + (size_t)ho*WOUT + wo;

    for (int t0 = 0; t0 < T_; t0 += 4) {
        float acc[GO][WOT][4];
        #pragma unroll
        for (int g = 0; g < GO; g++)
            #pragma unroll
            for (int ww = 0; ww < WOT; ww++)
                #pragma unroll
                for (int tv = 0; tv < 4; tv++) acc[g][ww][tv] = bb[g];

        #pragma unroll 1
        for (int c = 0; c < CIN; c++) {
            #pragma unroll 1
            for (int kh = 0; kh < 5; kh++) {
                const float* ip = inb + (size_t)t0*TS_IN + ((size_t)c*HIN + ho + kh)*WIN;
                float v[WOT+4][4];
                #pragma unroll
                for (int j = 0; j < WOT+4; j++)
                    #pragma unroll
                    for (int tv = 0; tv < 4; tv++)
                        v[j][tv] = ip[j + tv*TS_IN];
                #pragma unroll
                for (int kw = 0; kw < 5; kw++) {
                    #pragma unroll
                    for (int g = 0; g < GO; g++) {
                        float w = ws[((og*GO+g)*CIN + c)*25 + kh*5 + kw];
                        #pragma unroll
                        for (int ww = 0; ww < WOT; ww++)
                            #pragma unroll
                            for (int tv = 0; tv < 4; tv++)
                                acc[g][ww][tv] += v[ww+kw][tv] * w;
                    }
                }
            }
        }
        // sequential LIF update over the 4 time steps
        #pragma unroll
        for (int tv = 0; tv < 4; tv++) {
            float* op = outb + (size_t)(t0+tv)*TS_OUT;
            #pragma unroll
            for (int g = 0; g < GO; g++)
                #pragma unroll
                for (int ww = 0; ww < WOT; ww++) {
                    float uu = u[g][ww] + acc[g][ww][tv];
                    float s = (uu >= 1.0f) ? 1.0f : 0.0f;
                    u[g][ww] = uu - s;
                    op[(size_t)g*HOUT*WOUT + ww] = s;
                }
        }
    }
}

// ---------------- fused 2x2 avg-pool + LIF spike scan ----------------
template<int C,int HIN>
__global__ void k_pool_spike(const float* __restrict__ in, float* __restrict__ out) {
    constexpr int HO = HIN/2;
    constexpr size_t TS_IN  = (size_t)N_*C*HIN*HIN;
    constexpr size_t TS_OUT = (size_t)N_*C*HO*HO;
    int idx = blockIdx.x * blockDim.x + threadIdx.x;
    if (idx >= N_*C*HO*HO) return;
    int wo = idx % HO; int t1 = idx / HO;
    int ho = t1 % HO;  int t2 = t1 / HO;
    int c  = t2 % C;   int n  = t2 / C;
    const float* ip = in + ((size_t)n*C + c)*HIN*HIN + (size_t)(2*ho)*HIN + 2*wo;
    float* op = out + ((size_t)n*C + c)*HO*HO + (size_t)ho*HO + wo;
    float u = 0.f;
    #pragma unroll 4
    for (int t = 0; t < T_; t++) {
        const float* p = ip + (size_t)t*TS_IN;
        float a = 0.25f*(p[0] + p[1] + p[HIN] + p[HIN+1]);
        u += a;
        float s = (u >= 1.0f) ? 1.0f : 0.0f;
        u -= s;
        op[(size_t)t*TS_OUT] = s;
    }
}

// ---------------- fc1 GEMM: z1[t][n][o] = p2[t][n][:512] . Wt1[:,o] + b ----------------
__global__ void k_fc1(const float* __restrict__ bf1) {
    __shared__ float sin_[4][512];
    int t0 = blockIdx.x*4, n = blockIdx.y, o = threadIdx.x;
    for (int i = o; i < 4*512; i += 128) {
        int tv = i >> 9, k = i & 511;
        sin_[tv][k] = g_p2[((size_t)(t0+tv)*N_ + n)*512 + k];
    }
    __syncthreads();
    float b = bf1[o];
    float acc[4] = {b, b, b, b};
    #pragma unroll 4
    for (int k = 0; k < 512; k++) {
        float w = g_wt1[k*128 + o];
        #pragma unroll
        for (int tv = 0; tv < 4; tv++) acc[tv] += sin_[tv][k] * w;
    }
    #pragma unroll
    for (int tv = 0; tv < 4; tv++)
        g_z1[((size_t)(t0+tv)*N_ + n)*128 + o] = acc[tv];
}

// ---------------- head: fc1 spike scan -> fc2 -> fc2 spike scan -> mean over T ----------------
__global__ void k_head(const float* __restrict__ Wf2, const float* __restrict__ bf2,
                       float* __restrict__ out) {
    int n = blockIdx.x, o = threadIdx.x;
    __shared__ float s1[128];
    __shared__ float w2[2][128];
    w2[0][o] = Wf2[o];
    w2[1][o] = Wf2[128 + o];
    float u1 = 0.f, u2 = 0.f, ssum = 0.f;
    float b2 = (o < 2) ? bf2[o] : 0.f;
    __syncthreads();
    for (int t = 0; t < T_; t++) {
        float z = g_z1[((size_t)t*N_ + n)*128 + o];
        u1 += z;
        float s = (u1 >= 1.0f) ? 1.0f : 0.0f;
        u1 -= s;
        s1[o] = s;
        __syncthreads();
        if (o < 2) {
            float d = b2;
            #pragma unroll 8
            for (int k = 0; k < 128; k++) d += s1[k] * w2[o][k];
            u2 += d;
            float s2 = (u2 >= 1.0f) ? 1.0f : 0.0f;
            u2 -= s2;
            ssum += s2;
        }
        __syncthreads();
    }
    if (o < 2) out[n*2 + o] = ssum * (1.0f / T_);
}

// ---------------- launch ----------------
extern "C" void kernel_launch(void* const* d_in, const int* in_sizes, int n_in,
                              void* d_out, int out_size) {
    (void)in_sizes; (void)n_in; (void)out_size;
    const float* x   = (const float*)d_in[0];
    const float* Wc1 = (const float*)d_in[1];
    const float* bc1 = (const float*)d_in[2];
    const float* Wc2 = (const float*)d_in[3];
    const float* bc2 = (const float*)d_in[4];
    const float* Wc3 = (const float*)d_in[5];
    const float* bc3 = (const float*)d_in[6];
    const float* Wf1 = (const float*)d_in[7];
    const float* bf1 = (const float*)d_in[8];
    const float* Wf2 = (const float*)d_in[9];
    const float* bf2 = (const float*)d_in[10];
    float* out = (float*)d_out;

    float *p_xt, *p_h1, *p_h2, *p_p1, *p_h3, *p_p2;
    cudaGetSymbolAddress((void**)&p_xt, g_xt);
    cudaGetSymbolAddress((void**)&p_h1, g_h1);
    cudaGetSymbolAddress((void**)&p_h2, g_h2);
    cudaGetSymbolAddress((void**)&p_p1, g_p1);
    cudaGetSymbolAddress((void**)&p_h3, g_h3);
    cudaGetSymbolAddress((void**)&p_p2, g_p2);

    auto c1 = k_conv_spike<1,16,32,32,4,2,2>;    // 112 thr/blk
    auto c2 = k_conv_spike<16,32,28,28,4,2,2>;   // 192 thr/blk
    auto c3 = k_conv_spike<32,32,12,12,2,1,2>;   // 256 thr/blk
    cudaFuncSetAttribute(c2, cudaFuncAttributeMaxDynamicSharedMemorySize, 32*16*25*4);
    cudaFuncSetAttribute(c3, cudaFuncAttributeMaxDynamicSharedMemorySize, 32*32*25*4);

    k_transpose_x<<<(N_*1024 + 255)/256, 256>>>(x);
    k_transpose_wf1<<<(128*512 + 255)/256, 256>>>(Wf1);

    c1<<<dim3(14, N_), dim3(56, 2), 16*1*25*4>>>(p_xt, Wc1, bc1, p_h1);
    c2<<<dim3(12, N_), dim3(96, 2), 32*16*25*4>>>(p_h1, Wc2, bc2, p_h2);
    k_pool_spike<32,24><<<(N_*32*12*12 + 255)/256, 256>>>(p_h2, p_p1);
    c3<<<dim3(4, N_), dim3(128, 2), 32*32*25*4>>>(p_p1, Wc3, bc3, p_h3);
    k_pool_spike<32,8><<<(N_*32*4*4 + 255)/256, 256>>>(p_h3, p_p2);

    k_fc1<<<dim3(T_/4, N_), 128>>>(bf1);
    k_head<<<N_, 128>>>(Wf2, bf2, out);
}

// round 2
// speedup vs baseline: 1.0729x; 1.0729x over previous
#include <cuda_runtime.h>

#define N_ 32
#define T_ 48

// ---------------- scratch (t-major: [T][N][C][H][W]) ----------------
__device__ float g_xt[(size_t)T_*N_*32*32];          // x transposed (C=1)
__device__ float g_h1[(size_t)T_*N_*16*28*28];       // conv1 spikes
__device__ float g_h2[(size_t)T_*N_*32*24*24];       // conv2 spikes
__device__ float g_p1[(size_t)T_*N_*32*12*12];       // pool1 spikes
__device__ float g_h3[(size_t)T_*N_*32*8*8];         // conv3 spikes
__device__ float g_p2[(size_t)T_*N_*32*4*4];         // pool2 spikes
__device__ float g_wt1[512*128];                     // Wf1 transposed [k][o]
__device__ float g_z1[(size_t)T_*N_*128];            // fc1 pre-activations

// ---------------- transpose x: [N,1,32,32,T] -> [T][N][32][32] ----------------
__global__ void k_transpose_x(const float* __restrict__ x) {
    int idx = blockIdx.x * blockDim.x + threadIdx.x;
    if (idx >= N_*32*32) return;
    int n = idx >> 10, hw = idx & 1023;
    const float* xp = x + (size_t)idx * T_;
    #pragma unroll
    for (int t = 0; t < T_; t++)
        g_xt[((size_t)t*N_ + n)*1024 + hw] = xp[t];
}

// ---------------- transpose Wf1: [128][512] -> [512][128] ----------------
__global__ void k_transpose_wf1(const float* __restrict__ Wf1) {
    int idx = blockIdx.x * blockDim.x + threadIdx.x;
    if (idx >= 128*512) return;
    int o = idx >> 9, k = idx & 511;
    g_wt1[k*128 + o] = Wf1[idx];
}

// ---------------- fused 5x5 VALID conv + LIF spike scan ----------------
// Smem weights are stored CHANNEL-LAST: ws[(c*25 + kh*5 + kw)*COUT + oc]
// so lanes differing in og stride GO words -> conflict-free broadcast.
template<int CIN,int COUT,int HIN,int WIN,int GO,int WOT,int HOT,int TV>
__global__ void k_conv_spike(const float* __restrict__ in,
                             const float* __restrict__ Wc,
                             const float* __restrict__ bc,
                             float* __restrict__ out) {
    constexpr int HOUT = HIN-4, WOUT = WIN-4;
    constexpr int NWG  = WOUT/WOT;
    constexpr int NOG  = COUT/GO;
    constexpr int LANES = NWG*NOG;
    constexpr size_t TS_IN  = (size_t)N_*CIN*HIN*WIN;
    constexpr size_t TS_OUT = (size_t)N_*COUT*HOUT*WOUT;
    extern __shared__ float ws[];   // CIN*25*COUT, channel-last
    {
        int tid = threadIdx.y*LANES + threadIdx.x;
        for (int i = tid; i < COUT*CIN*25; i += LANES*HOT) {
            int oc = i % COUT;
            int ck = i / COUT;          // c*25 + k
            ws[i] = Wc[oc*CIN*25 + ck];
        }
    }
    __syncthreads();

    int wg = threadIdx.x % NWG;
    int og = threadIdx.x / NWG;
    int wo = wg * WOT;
    int ho = blockIdx.x*HOT + threadIdx.y;
    int n  = blockIdx.y;

    float u[GO][WOT];
    float bb[GO];
    #pragma unroll
    for (int g = 0; g < GO; g++) {
        bb[g] = bc[og*GO + g];
        #pragma unroll
        for (int ww = 0; ww < WOT; ww++) u[g][ww] = 0.f;
    }

    const float* inb = in + (size_t)n*CIN*HIN*WIN + wo;
    float* outb = out + (size_t)n*COUT*HOUT*WOUT
                      + (size_t)og*GO*HOUT*WOUT + (size_t)ho*WOUT + wo;

    for (int t0 = 0; t0 < T_; t0 += TV) {
        float acc[GO][WOT][TV];
        #pragma unroll
        for (int g = 0; g < GO; g++)
            #pragma unroll
            for (int ww = 0; ww < WOT; ww++)
                #pragma unroll
                for (int tv = 0; tv < TV; tv++) acc[g][ww][tv] = bb[g];

        #pragma unroll 1
        for (int c = 0; c < CIN; c++) {
            #pragma unroll 1
            for (int kh = 0; kh < 5; kh++) {
                const float* ip = inb + (size_t)t0*TS_IN + ((size_t)c*HIN + ho + kh)*WIN;
                float v[WOT+4][TV];
                if constexpr ((WOT & 1) == 0 && (WIN & 1) == 0) {
                    // 8B-aligned (wo even, WIN even): float2 loads
                    #pragma unroll
                    for (int tv = 0; tv < TV; tv++) {
                        const float2* p2 = reinterpret_cast<const float2*>(ip + tv*TS_IN);
                        #pragma unroll
                        for (int j2 = 0; j2 < (WOT+4)/2; j2++) {
                            float2 d = p2[j2];
                            v[2*j2][tv]   = d.x;
                            v[2*j2+1][tv] = d.y;
                        }
                    }
                } else {
                    #pragma unroll
                    for (int j = 0; j < WOT+4; j++)
                        #pragma unroll
                        for (int tv = 0; tv < TV; tv++)
                            v[j][tv] = ip[j + tv*TS_IN];
                }
                #pragma unroll
                for (int kw = 0; kw < 5; kw++) {
                    #pragma unroll
                    for (int g = 0; g < GO; g++) {
                        float w = ws[((c*5 + kh)*5 + kw)*COUT + og*GO + g];
                        #pragma unroll
                        for (int ww = 0; ww < WOT; ww++)
                            #pragma unroll
                            for (int tv = 0; tv < TV; tv++)
                                acc[g][ww][tv] += v[ww+kw][tv] * w;
                    }
                }
            }
        }
        // sequential LIF update over the TV time steps
        #pragma unroll
        for (int tv = 0; tv < TV; tv++) {
            float* op = outb + (size_t)(t0+tv)*TS_OUT;
            #pragma unroll
            for (int g = 0; g < GO; g++)
                #pragma unroll
                for (int ww = 0; ww < WOT; ww++) {
                    float uu = u[g][ww] + acc[g][ww][tv];
                    float s = (uu >= 1.0f) ? 1.0f : 0.0f;
                    u[g][ww] = uu - s;
                    op[(size_t)g*HOUT*WOUT + ww] = s;
                }
        }
    }
}

// ---------------- fused 2x2 avg-pool + LIF spike scan ----------------
template<int C,int HIN>
__global__ void k_pool_spike(const float* __restrict__ in, float* __restrict__ out) {
    constexpr int HO = HIN/2;
    constexpr size_t TS_IN  = (size_t)N_*C*HIN*HIN;
    constexpr size_t TS_OUT = (size_t)N_*C*HO*HO;
    int idx = blockIdx.x * blockDim.x + threadIdx.x;
    if (idx >= N_*C*HO*HO) return;
    int wo = idx % HO; int t1 = idx / HO;
    int ho = t1 % HO;  int t2 = t1 / HO;
    int c  = t2 % C;   int n  = t2 / C;
    const float* ip = in + ((size_t)n*C + c)*HIN*HIN + (size_t)(2*ho)*HIN + 2*wo;
    float* op = out + ((size_t)n*C + c)*HO*HO + (size_t)ho*HO + wo;
    float u = 0.f;
    #pragma unroll 4
    for (int t = 0; t < T_; t++) {
        const float* p = ip + (size_t)t*TS_IN;
        float a = 0.25f*(p[0] + p[1] + p[HIN] + p[HIN+1]);
        u += a;
        float s = (u >= 1.0f) ? 1.0f : 0.0f;
        u -= s;
        op[(size_t)t*TS_OUT] = s;
    }
}

// ---------------- fc1 GEMM: z1[t][n][o] = p2[t][n][:512] . Wt1[:,o] + b ----------------
__global__ void k_fc1(const float* __restrict__ bf1) {
    __shared__ float sin_[4][512];
    int t0 = blockIdx.x*4, n = blockIdx.y, o = threadIdx.x;
    for (int i = o; i < 4*512; i += 128) {
        int tv = i >> 9, k = i & 511;
        sin_[tv][k] = g_p2[((size_t)(t0+tv)*N_ + n)*512 + k];
    }
    __syncthreads();
    float b = bf1[o];
    float acc[4] = {b, b, b, b};
    #pragma unroll 4
    for (int k = 0; k < 512; k++) {
        float w = g_wt1[k*128 + o];
        #pragma unroll
        for (int tv = 0; tv < 4; tv++) acc[tv] += sin_[tv][k] * w;
    }
    #pragma unroll
    for (int tv = 0; tv < 4; tv++)
        g_z1[((size_t)(t0+tv)*N_ + n)*128 + o] = acc[tv];
}

// ---------------- head: fc1 spike scan -> fc2 -> fc2 spike scan -> mean over T ----------------
__global__ void k_head(const float* __restrict__ Wf2, const float* __restrict__ bf2,
                       float* __restrict__ out) {
    int n = blockIdx.x, o = threadIdx.x;
    __shared__ float s1[128];
    __shared__ float w2[2][128];
    w2[0][o] = Wf2[o];
    w2[1][o] = Wf2[128 + o];
    float u1 = 0.f, u2 = 0.f, ssum = 0.f;
    float b2 = (o < 2) ? bf2[o] : 0.f;
    __syncthreads();
    for (int t = 0; t < T_; t++) {
        float z = g_z1[((size_t)t*N_ + n)*128 + o];
        u1 += z;
        float s = (u1 >= 1.0f) ? 1.0f : 0.0f;
        u1 -= s;
        s1[o] = s;
        __syncthreads();
        if (o < 2) {
            float d = b2;
            #pragma unroll 8
            for (int k = 0; k < 128; k++) d += s1[k] * w2[o][k];
            u2 += d;
            float s2 = (u2 >= 1.0f) ? 1.0f : 0.0f;
            u2 -= s2;
            ssum += s2;
        }
        __syncthreads();
    }
    if (o < 2) out[n*2 + o] = ssum * (1.0f / T_);
}

// ---------------- launch ----------------
extern "C" void kernel_launch(void* const* d_in, const int* in_sizes, int n_in,
                              void* d_out, int out_size) {
    (void)in_sizes; (void)n_in; (void)out_size;
    const float* x   = (const float*)d_in[0];
    const float* Wc1 = (const float*)d_in[1];
    const float* bc1 = (const float*)d_in[2];
    const float* Wc2 = (const float*)d_in[3];
    const float* bc2 = (const float*)d_in[4];
    const float* Wc3 = (const float*)d_in[5];
    const float* bc3 = (const float*)d_in[6];
    const float* Wf1 = (const float*)d_in[7];
    const float* bf1 = (const float*)d_in[8];
    const float* Wf2 = (const float*)d_in[9];
    const float* bf2 = (const float*)d_in[10];
    float* out = (float*)d_out;

    float *p_xt, *p_h1, *p_h2, *p_p1, *p_h3, *p_p2;
    cudaGetSymbolAddress((void**)&p_xt, g_xt);
    cudaGetSymbolAddress((void**)&p_h1, g_h1);
    cudaGetSymbolAddress((void**)&p_h2, g_h2);
    cudaGetSymbolAddress((void**)&p_p1, g_p1);
    cudaGetSymbolAddress((void**)&p_h3, g_h3);
    cudaGetSymbolAddress((void**)&p_p2, g_p2);

    auto c1 = k_conv_spike<1,16,32,32,4,2,2,6>;    // 112 thr/blk
    auto c2 = k_conv_spike<16,32,28,28,4,2,2,6>;   // 192 thr/blk
    auto c3 = k_conv_spike<32,32,12,12,2,1,2,4>;   // 256 thr/blk
    cudaFuncSetAttribute(c2, cudaFuncAttributeMaxDynamicSharedMemorySize, 32*16*25*4);
    cudaFuncSetAttribute(c3, cudaFuncAttributeMaxDynamicSharedMemorySize, 32*32*25*4);

    k_transpose_x<<<(N_*1024 + 255)/256, 256>>>(x);
    k_transpose_wf1<<<(128*512 + 255)/256, 256>>>(Wf1);

    c1<<<dim3(14, N_), dim3(56, 2), 16*1*25*4>>>(p_xt, Wc1, bc1, p_h1);
    c2<<<dim3(12, N_), dim3(96, 2), 32*16*25*4>>>(p_h1, Wc2, bc2, p_h2);
    k_pool_spike<32,24><<<(N_*32*12*12 + 255)/256, 256>>>(p_h2, p_p1);
    c3<<<dim3(4, N_), dim3(128, 2), 32*32*25*4>>>(p_p1, Wc3, bc3, p_h3);
    k_pool_spike<32,8><<<(N_*32*4*4 + 255)/256, 256>>>(p_h3, p_p2);

    k_fc1<<<dim3(T_/4, N_), 128>>>(bf1);
    k_head<<<N_, 128>>>(Wf2, bf2, out);
}

// round 3
// speedup vs baseline: 1.9145x; 1.7844x over previous
#include <cuda_runtime.h>

#define N_ 32
#define T_ 48

// ---------------- scratch (t-major: [T][N][C][H][W]) ----------------
__device__ float g_xt[(size_t)T_*N_*32*32];          // x transposed (C=1)
__device__ float g_z1c[(size_t)T_*N_*16*28*28];      // conv1 pre-acts
__device__ float g_h1[(size_t)T_*N_*16*28*28];       // conv1 spikes
__device__ float g_z2c[(size_t)T_*N_*32*24*24];      // conv2 pre-acts
__device__ float g_h2[(size_t)T_*N_*32*24*24];       // conv2 spikes
__device__ float g_p1[(size_t)T_*N_*32*12*12];       // pool1 spikes
__device__ float g_z3c[(size_t)T_*N_*32*8*8];        // conv3 pre-acts
__device__ float g_h3[(size_t)T_*N_*32*8*8];         // conv3 spikes
__device__ float g_p2[(size_t)T_*N_*32*4*4];         // pool2 spikes
__device__ float g_wt1[512*128];                     // Wf1 transposed [k][o]
__device__ float g_z1[(size_t)T_*N_*128];            // fc1 pre-activations

// ---------------- transpose x: [N,1,32,32,T] -> [T][N][32][32] ----------------
__global__ void k_transpose_x(const float* __restrict__ x) {
    int idx = blockIdx.x * blockDim.x + threadIdx.x;
    if (idx >= N_*32*32) return;
    int n = idx >> 10, hw = idx & 1023;
    const float* xp = x + (size_t)idx * T_;
    #pragma unroll
    for (int t = 0; t < T_; t++)
        g_xt[((size_t)t*N_ + n)*1024 + hw] = xp[t];
}

// ---------------- transpose Wf1: [128][512] -> [512][128] ----------------
__global__ void k_transpose_wf1(const float* __restrict__ Wf1) {
    int idx = blockIdx.x * blockDim.x + threadIdx.x;
    if (idx >= 128*512) return;
    int o = idx >> 9, k = idx & 511;
    g_wt1[k*128 + o] = Wf1[idx];
}

// ---------------- 5x5 VALID conv (pre-activation only; parallel over T) ----------------
// Smem weights channel-last: ws[(c*25+k)*COUT + oc] -> conflict-free broadcast.
// Each thread: GO oc x WOT wo x TV t at one (n, ho).
template<int CIN,int COUT,int HIN,int WIN,int GO,int WOT,int HOT,int TV>
__global__ void k_conv(const float* __restrict__ in,
                       const float* __restrict__ Wc,
                       const float* __restrict__ bc,
                       float* __restrict__ z) {
    constexpr int HOUT = HIN-4, WOUT = WIN-4;
    constexpr int NWG  = WOUT/WOT;
    constexpr int NOG  = COUT/GO;
    constexpr int LANES = NWG*NOG;
    constexpr int HBLK = HOUT/HOT;
    constexpr size_t TS_IN  = (size_t)N_*CIN*HIN*WIN;
    constexpr size_t TS_OUT = (size_t)N_*COUT*HOUT*WOUT;
    extern __shared__ float ws[];   // CIN*25*COUT, channel-last
    {
        int tid = threadIdx.y*LANES + threadIdx.x;
        for (int i = tid; i < COUT*CIN*25; i += LANES*HOT) {
            int oc = i % COUT;
            int ck = i / COUT;
            ws[i] = Wc[oc*CIN*25 + ck];
        }
    }
    __syncthreads();

    int hb = blockIdx.x % HBLK;
    int t0 = (blockIdx.x / HBLK) * TV;
    int n  = blockIdx.y;
    int wg = threadIdx.x % NWG;
    int og = threadIdx.x / NWG;
    int wo = wg * WOT;
    int ho = hb*HOT + threadIdx.y;

    float acc[GO][WOT][TV];
    #pragma unroll
    for (int g = 0; g < GO; g++) {
        float b = bc[og*GO + g];
        #pragma unroll
        for (int ww = 0; ww < WOT; ww++)
            #pragma unroll
            for (int tv = 0; tv < TV; tv++) acc[g][ww][tv] = b;
    }

    const float* inb = in + (size_t)t0*TS_IN + (size_t)n*CIN*HIN*WIN + wo;

    #pragma unroll 1
    for (int c = 0; c < CIN; c++) {
        #pragma unroll 1
        for (int kh = 0; kh < 5; kh++) {
            const float* ip = inb + ((size_t)c*HIN + ho + kh)*WIN;
            float v[WOT+4][TV];
            // wo and WIN are even in all instantiations -> 8B-aligned float2 loads
            #pragma unroll
            for (int tv = 0; tv < TV; tv++) {
                const float2* p2 = reinterpret_cast<const float2*>(ip + (size_t)tv*TS_IN);
                #pragma unroll
                for (int j2 = 0; j2 < (WOT+4)/2; j2++) {
                    float2 d = p2[j2];
                    v[2*j2][tv]   = d.x;
                    v[2*j2+1][tv] = d.y;
                }
            }
            #pragma unroll
            for (int kw = 0; kw < 5; kw++) {
                #pragma unroll
                for (int g = 0; g < GO; g++) {
                    float w = ws[((c*5 + kh)*5 + kw)*COUT + og*GO + g];
                    #pragma unroll
                    for (int ww = 0; ww < WOT; ww++)
                        #pragma unroll
                        for (int tv = 0; tv < TV; tv++)
                            acc[g][ww][tv] += v[ww+kw][tv] * w;
                }
            }
        }
    }

    float* zb = z + (size_t)t0*TS_OUT + (size_t)n*COUT*HOUT*WOUT
                  + (size_t)og*GO*HOUT*WOUT + (size_t)ho*WOUT + wo;
    #pragma unroll
    for (int tv = 0; tv < TV; tv++)
        #pragma unroll
        for (int g = 0; g < GO; g++)
            #pragma unroll
            for (int ww = 0; ww < WOT; ww++)
                zb[(size_t)tv*TS_OUT + (size_t)g*HOUT*WOUT + ww] = acc[g][ww][tv];
}

// ---------------- LIF scan over T: z -> spikes ----------------
template<int SZ>   // SZ = N*C*H*W per time step
__global__ void k_scan(const float* __restrict__ z, float* __restrict__ s_out) {
    int idx = blockIdx.x * blockDim.x + threadIdx.x;
    if (idx >= SZ) return;
    float u = 0.f;
    #pragma unroll 4
    for (int t = 0; t < T_; t++) {
        u += z[(size_t)t*SZ + idx];
        float s = (u >= 1.0f) ? 1.0f : 0.0f;
        u -= s;
        s_out[(size_t)t*SZ + idx] = s;
    }
}

// ---------------- fused 2x2 avg-pool + LIF spike scan ----------------
template<int C,int HIN>
__global__ void k_pool_spike(const float* __restrict__ in, float* __restrict__ out) {
    constexpr int HO = HIN/2;
    constexpr size_t TS_IN  = (size_t)N_*C*HIN*HIN;
    constexpr size_t TS_OUT = (size_t)N_*C*HO*HO;
    int idx = blockIdx.x * blockDim.x + threadIdx.x;
    if (idx >= N_*C*HO*HO) return;
    int wo = idx % HO; int t1 = idx / HO;
    int ho = t1 % HO;  int t2 = t1 / HO;
    int c  = t2 % C;   int n  = t2 / C;
    const float* ip = in + ((size_t)n*C + c)*HIN*HIN + (size_t)(2*ho)*HIN + 2*wo;
    float* op = out + ((size_t)n*C + c)*HO*HO + (size_t)ho*HO + wo;
    float u = 0.f;
    #pragma unroll 4
    for (int t = 0; t < T_; t++) {
        const float* p = ip + (size_t)t*TS_IN;
        float a = 0.25f*(p[0] + p[1] + p[HIN] + p[HIN+1]);
        u += a;
        float s = (u >= 1.0f) ? 1.0f : 0.0f;
        u -= s;
        op[(size_t)t*TS_OUT] = s;
    }
}

// ---------------- fc1 GEMM: z1[t][n][o] = p2[t][n][:512] . Wt1[:,o] + b ----------------
__global__ void k_fc1(const float* __restrict__ bf1) {
    __shared__ float sin_[4][512];
    int t0 = blockIdx.x*4, n = blockIdx.y, o = threadIdx.x;
    for (int i = o; i < 4*512; i += 128) {
        int tv = i >> 9, k = i & 511;
        sin_[tv][k] = g_p2[((size_t)(t0+tv)*N_ + n)*512 + k];
    }
    __syncthreads();
    float b = bf1[o];
    float acc[4] = {b, b, b, b};
    #pragma unroll 4
    for (int k = 0; k < 512; k++) {
        float w = g_wt1[k*128 + o];
        #pragma unroll
        for (int tv = 0; tv < 4; tv++) acc[tv] += sin_[tv][k] * w;
    }
    #pragma unroll
    for (int tv = 0; tv < 4; tv++)
        g_z1[((size_t)(t0+tv)*N_ + n)*128 + o] = acc[tv];
}

// ---------------- head: fc1 spike scan -> fc2 -> fc2 spike scan -> mean over T ----------------
__global__ void k_head(const float* __restrict__ Wf2, const float* __restrict__ bf2,
                       float* __restrict__ out) {
    int n = blockIdx.x, o = threadIdx.x;
    __shared__ float s1[128];
    __shared__ float w2[2][128];
    w2[0][o] = Wf2[o];
    w2[1][o] = Wf2[128 + o];
    float u1 = 0.f, u2 = 0.f, ssum = 0.f;
    float b2 = (o < 2) ? bf2[o] : 0.f;
    __syncthreads();
    for (int t = 0; t < T_; t++) {
        float z = g_z1[((size_t)t*N_ + n)*128 + o];
        u1 += z;
        float s = (u1 >= 1.0f) ? 1.0f : 0.0f;
        u1 -= s;
        s1[o] = s;
        __syncthreads();
        if (o < 2) {
            float d = b2;
            #pragma unroll 8
            for (int k = 0; k < 128; k++) d += s1[k] * w2[o][k];
            u2 += d;
            float s2 = (u2 >= 1.0f) ? 1.0f : 0.0f;
            u2 -= s2;
            ssum += s2;
        }
        __syncthreads();
    }
    if (o < 2) out[n*2 + o] = ssum * (1.0f / T_);
}

// ---------------- launch ----------------
extern "C" void kernel_launch(void* const* d_in, const int* in_sizes, int n_in,
                              void* d_out, int out_size) {
    (void)in_sizes; (void)n_in; (void)out_size;
    const float* x   = (const float*)d_in[0];
    const float* Wc1 = (const float*)d_in[1];
    const float* bc1 = (const float*)d_in[2];
    const float* Wc2 = (const float*)d_in[3];
    const float* bc2 = (const float*)d_in[4];
    const float* Wc3 = (const float*)d_in[5];
    const float* bc3 = (const float*)d_in[6];
    const float* Wf1 = (const float*)d_in[7];
    const float* bf1 = (const float*)d_in[8];
    const float* Wf2 = (const float*)d_in[9];
    const float* bf2 = (const float*)d_in[10];
    float* out = (float*)d_out;

    float *p_xt, *p_z1c, *p_h1, *p_z2c, *p_h2, *p_p1, *p_z3c, *p_h3, *p_p2;
    cudaGetSymbolAddress((void**)&p_xt,  g_xt);
    cudaGetSymbolAddress((void**)&p_z1c, g_z1c);
    cudaGetSymbolAddress((void**)&p_h1,  g_h1);
    cudaGetSymbolAddress((void**)&p_z2c, g_z2c);
    cudaGetSymbolAddress((void**)&p_h2,  g_h2);
    cudaGetSymbolAddress((void**)&p_p1,  g_p1);
    cudaGetSymbolAddress((void**)&p_z3c, g_z3c);
    cudaGetSymbolAddress((void**)&p_h3,  g_h3);
    cudaGetSymbolAddress((void**)&p_p2,  g_p2);

    // conv1: CIN=1, GO=2, WOT=4, HOT=4, TV=2 -> block (56,4)=224 thr
    auto c1 = k_conv<1,16,32,32,2,4,4,2>;
    // conv2: CIN=16, GO=4, WOT=4, HOT=4, TV=2 -> block (48,4)=192 thr
    auto c2 = k_conv<16,32,28,28,4,4,4,2>;
    // conv3: CIN=32, GO=4, WOT=2, HOT=8, TV=4 -> block (32,8)=256 thr
    auto c3 = k_conv<32,32,12,12,4,2,8,4>;
    cudaFuncSetAttribute(c2, cudaFuncAttributeMaxDynamicSharedMemorySize, 32*16*25*4);
    cudaFuncSetAttribute(c3, cudaFuncAttributeMaxDynamicSharedMemorySize, 32*32*25*4);

    k_transpose_x<<<(N_*1024 + 255)/256, 256>>>(x);
    k_transpose_wf1<<<(128*512 + 255)/256, 256>>>(Wf1);

    constexpr int SZ1 = N_*16*28*28;
    constexpr int SZ2 = N_*32*24*24;
    constexpr int SZ3 = N_*32*8*8;

    c1<<<dim3(7*(T_/2), N_), dim3(56, 4), 16*1*25*4>>>(p_xt, Wc1, bc1, p_z1c);
    k_scan<SZ1><<<(SZ1 + 255)/256, 256>>>(p_z1c, p_h1);

    c2<<<dim3(6*(T_/2), N_), dim3(48, 4), 32*16*25*4>>>(p_h1, Wc2, bc2, p_z2c);
    k_scan<SZ2><<<(SZ2 + 255)/256, 256>>>(p_z2c, p_h2);

    k_pool_spike<32,24><<<(N_*32*12*12 + 255)/256, 256>>>(p_h2, p_p1);

    c3<<<dim3(1*(T_/4), N_), dim3(32, 8), 32*32*25*4>>>(p_p1, Wc3, bc3, p_z3c);
    k_scan<SZ3><<<(SZ3 + 255)/256, 256>>>(p_z3c, p_h3);

    k_pool_spike<32,8><<<(N_*32*4*4 + 255)/256, 256>>>(p_h3, p_p2);

    k_fc1<<<dim3(T_/4, N_), 128>>>(bf1);
    k_head<<<N_, 128>>>(Wf2, bf2, out);
}

// round 4
// speedup vs baseline: 1.9581x; 1.0228x over previous
#include <cuda_runtime.h>

#define N_ 32
#define T_ 48

// ---------------- scratch (t-major: [T][N][C][H][W]) ----------------
__device__ float g_xt[(size_t)T_*N_*32*32];          // x transposed (C=1)
__device__ float g_z1c[(size_t)T_*N_*16*28*28];      // conv1 pre-acts
__device__ float g_h1[(size_t)T_*N_*16*28*28];       // conv1 spikes
__device__ float g_z2c[(size_t)T_*N_*32*24*24];      // conv2 pre-acts
__device__ float g_p1[(size_t)T_*N_*32*12*12];       // pool1 spikes
__device__ float g_z3c[(size_t)T_*N_*32*8*8];        // conv3 pre-acts
__device__ float g_p2[(size_t)T_*N_*32*4*4];         // pool2 spikes
__device__ float g_wt1[512*128];                     // Wf1 transposed [k][o]
__device__ float g_z1[(size_t)T_*N_*128];            // fc1 pre-activations

// ---------------- transpose x: [N,1,32,32,T] -> [T][N][32][32] ----------------
__global__ void k_transpose_x(const float* __restrict__ x) {
    int idx = blockIdx.x * blockDim.x + threadIdx.x;
    if (idx >= N_*32*32) return;
    int n = idx >> 10, hw = idx & 1023;
    const float* xp = x + (size_t)idx * T_;
    #pragma unroll
    for (int t = 0; t < T_; t++)
        g_xt[((size_t)t*N_ + n)*1024 + hw] = xp[t];
}

// ---------------- transpose Wf1: [128][512] -> [512][128] ----------------
__global__ void k_transpose_wf1(const float* __restrict__ Wf1) {
    int idx = blockIdx.x * blockDim.x + threadIdx.x;
    if (idx >= 128*512) return;
    int o = idx >> 9, k = idx & 511;
    g_wt1[k*128 + o] = Wf1[idx];
}

// ---------------- 5x5 VALID conv (pre-activation only; parallel over T) ----------------
// Smem weights channel-last: ws[(c*25+k)*COUT + oc] -> conflict-free broadcast.
template<int CIN,int COUT,int HIN,int WIN,int GO,int WOT,int HOT,int TV>
__global__ void k_conv(const float* __restrict__ in,
                       const float* __restrict__ Wc,
                       const float* __restrict__ bc,
                       float* __restrict__ z) {
    constexpr int HOUT = HIN-4, WOUT = WIN-4;
    constexpr int NWG  = WOUT/WOT;
    constexpr int NOG  = COUT/GO;
    constexpr int LANES = NWG*NOG;
    constexpr int HBLK = HOUT/HOT;
    constexpr size_t TS_IN  = (size_t)N_*CIN*HIN*WIN;
    constexpr size_t TS_OUT = (size_t)N_*COUT*HOUT*WOUT;
    extern __shared__ float ws[];   // CIN*25*COUT, channel-last
    {
        int tid = threadIdx.y*LANES + threadIdx.x;
        for (int i = tid; i < COUT*CIN*25; i += LANES*HOT) {
            int oc = i % COUT;
            int ck = i / COUT;
            ws[i] = Wc[oc*CIN*25 + ck];
        }
    }
    __syncthreads();

    int hb = blockIdx.x % HBLK;
    int t0 = (blockIdx.x / HBLK) * TV;
    int n  = blockIdx.y;
    int wg = threadIdx.x % NWG;
    int og = threadIdx.x / NWG;
    int wo = wg * WOT;
    int ho = hb*HOT + threadIdx.y;

    float acc[GO][WOT][TV];
    #pragma unroll
    for (int g = 0; g < GO; g++) {
        float b = bc[og*GO + g];
        #pragma unroll
        for (int ww = 0; ww < WOT; ww++)
            #pragma unroll
            for (int tv = 0; tv < TV; tv++) acc[g][ww][tv] = b;
    }

    const float* inb = in + (size_t)t0*TS_IN + (size_t)n*CIN*HIN*WIN + wo;

    #pragma unroll 1
    for (int c = 0; c < CIN; c++) {
        #pragma unroll 1
        for (int kh = 0; kh < 5; kh++) {
            const float* ip = inb + ((size_t)c*HIN + ho + kh)*WIN;
            float v[WOT+4][TV];
            // wo and WIN even in all instantiations -> 8B-aligned float2 loads
            #pragma unroll
            for (int tv = 0; tv < TV; tv++) {
                const float2* p2 = reinterpret_cast<const float2*>(ip + (size_t)tv*TS_IN);
                #pragma unroll
                for (int j2 = 0; j2 < (WOT+4)/2; j2++) {
                    float2 d = p2[j2];
                    v[2*j2][tv]   = d.x;
                    v[2*j2+1][tv] = d.y;
                }
            }
            #pragma unroll
            for (int kw = 0; kw < 5; kw++) {
                #pragma unroll
                for (int g = 0; g < GO; g++) {
                    float w = ws[((c*5 + kh)*5 + kw)*COUT + og*GO + g];
                    #pragma unroll
                    for (int ww = 0; ww < WOT; ww++)
                        #pragma unroll
                        for (int tv = 0; tv < TV; tv++)
                            acc[g][ww][tv] += v[ww+kw][tv] * w;
                }
            }
        }
    }

    float* zb = z + (size_t)t0*TS_OUT + (size_t)n*COUT*HOUT*WOUT
                  + (size_t)og*GO*HOUT*WOUT + (size_t)ho*WOUT + wo;
    #pragma unroll
    for (int tv = 0; tv < TV; tv++)
        #pragma unroll
        for (int g = 0; g < GO; g++) {
            float* op = zb + (size_t)tv*TS_OUT + (size_t)g*HOUT*WOUT;
            #pragma unroll
            for (int j2 = 0; j2 < WOT/2; j2++) {
                float2 d; d.x = acc[g][2*j2][tv]; d.y = acc[g][2*j2+1][tv];
                reinterpret_cast<float2*>(op)[j2] = d;
            }
        }
}

// ---------------- LIF scan over T: z -> spikes ----------------
template<int SZ>   // SZ = N*C*H*W per time step
__global__ void k_scan(const float* __restrict__ z, float* __restrict__ s_out) {
    int idx = blockIdx.x * blockDim.x + threadIdx.x;
    if (idx >= SZ) return;
    float u = 0.f;
    #pragma unroll 4
    for (int t = 0; t < T_; t++) {
        u += z[(size_t)t*SZ + idx];
        float s = (u >= 1.0f) ? 1.0f : 0.0f;
        u -= s;
        s_out[(size_t)t*SZ + idx] = s;
    }
}

// ---------------- fused LIF scan + 2x2 avg-pool + LIF scan ----------------
// Reads conv pre-acts z directly: per pool pixel keep 4 input membrane states
// and 1 pool membrane state; writes only pooled spikes.
template<int C,int HIN>
__global__ void k_scanpool(const float* __restrict__ z, float* __restrict__ out) {
    constexpr int HO = HIN/2;
    constexpr size_t TS_IN  = (size_t)N_*C*HIN*HIN;
    constexpr size_t TS_OUT = (size_t)N_*C*HO*HO;
    int idx = blockIdx.x * blockDim.x + threadIdx.x;
    if (idx >= N_*C*HO*HO) return;
    int wo = idx % HO; int t1 = idx / HO;
    int ho = t1 % HO;  int t2 = t1 / HO;
    int c  = t2 % C;   int n  = t2 / C;
    const float* ip = z + ((size_t)n*C + c)*HIN*HIN + (size_t)(2*ho)*HIN + 2*wo;
    float* op = out + ((size_t)n*C + c)*HO*HO + (size_t)ho*HO + wo;
    float u0 = 0.f, u1 = 0.f, u2 = 0.f, u3 = 0.f, up = 0.f;
    #pragma unroll 4
    for (int t = 0; t < T_; t++) {
        const float* p = ip + (size_t)t*TS_IN;
        float2 r0 = *reinterpret_cast<const float2*>(p);
        float2 r1 = *reinterpret_cast<const float2*>(p + HIN);
        u0 += r0.x; float s0 = (u0 >= 1.0f) ? 1.0f : 0.0f; u0 -= s0;
        u1 += r0.y; float s1 = (u1 >= 1.0f) ? 1.0f : 0.0f; u1 -= s1;
        u2 += r1.x; float s2 = (u2 >= 1.0f) ? 1.0f : 0.0f; u2 -= s2;
        u3 += r1.y; float s3 = (u3 >= 1.0f) ? 1.0f : 0.0f; u3 -= s3;
        up += 0.25f*(s0 + s1 + s2 + s3);
        float sp = (up >= 1.0f) ? 1.0f : 0.0f; up -= sp;
        op[(size_t)t*TS_OUT] = sp;
    }
}

// ---------------- fc1 GEMM: z1[t][n][o] = p2[t][n][:512] . Wt1[:,o] + b ----------------
__global__ void k_fc1(const float* __restrict__ bf1) {
    __shared__ float sin_[4][512];
    int t0 = blockIdx.x*4, n = blockIdx.y, o = threadIdx.x;
    for (int i = o; i < 4*512; i += 128) {
        int tv = i >> 9, k = i & 511;
        sin_[tv][k] = g_p2[((size_t)(t0+tv)*N_ + n)*512 + k];
    }
    __syncthreads();
    float b = bf1[o];
    float acc[4] = {b, b, b, b};
    #pragma unroll 4
    for (int k = 0; k < 512; k++) {
        float w = g_wt1[k*128 + o];
        #pragma unroll
        for (int tv = 0; tv < 4; tv++) acc[tv] += sin_[tv][k] * w;
    }
    #pragma unroll
    for (int tv = 0; tv < 4; tv++)
        g_z1[((size_t)(t0+tv)*N_ + n)*128 + o] = acc[tv];
}

// ---------------- head: fc1 spike scan -> fc2 -> fc2 spike scan -> mean over T ----------------
__global__ void k_head(const float* __restrict__ Wf2, const float* __restrict__ bf2,
                       float* __restrict__ out) {
    int n = blockIdx.x, o = threadIdx.x;
    __shared__ float s1[128];
    __shared__ float w2[2][128];
    w2[0][o] = Wf2[o];
    w2[1][o] = Wf2[128 + o];
    float u1 = 0.f, u2 = 0.f, ssum = 0.f;
    float b2 = (o < 2) ? bf2[o] : 0.f;
    __syncthreads();
    for (int t = 0; t < T_; t++) {
        float z = g_z1[((size_t)t*N_ + n)*128 + o];
        u1 += z;
        float s = (u1 >= 1.0f) ? 1.0f : 0.0f;
        u1 -= s;
        s1[o] = s;
        __syncthreads();
        if (o < 2) {
            float d = b2;
            #pragma unroll 8
            for (int k = 0; k < 128; k++) d += s1[k] * w2[o][k];
            u2 += d;
            float s2 = (u2 >= 1.0f) ? 1.0f : 0.0f;
            u2 -= s2;
            ssum += s2;
        }
        __syncthreads();
    }
    if (o < 2) out[n*2 + o] = ssum * (1.0f / T_);
}

// ---------------- launch ----------------
extern "C" void kernel_launch(void* const* d_in, const int* in_sizes, int n_in,
                              void* d_out, int out_size) {
    (void)in_sizes; (void)n_in; (void)out_size;
    const float* x   = (const float*)d_in[0];
    const float* Wc1 = (const float*)d_in[1];
    const float* bc1 = (const float*)d_in[2];
    const float* Wc2 = (const float*)d_in[3];
    const float* bc2 = (const float*)d_in[4];
    const float* Wc3 = (const float*)d_in[5];
    const float* bc3 = (const float*)d_in[6];
    const float* Wf1 = (const float*)d_in[7];
    const float* bf1 = (const float*)d_in[8];
    const float* Wf2 = (const float*)d_in[9];
    const float* bf2 = (const float*)d_in[10];
    float* out = (float*)d_out;

    float *p_xt, *p_z1c, *p_h1, *p_z2c, *p_p1, *p_z3c, *p_p2;
    cudaGetSymbolAddress((void**)&p_xt,  g_xt);
    cudaGetSymbolAddress((void**)&p_z1c, g_z1c);
    cudaGetSymbolAddress((void**)&p_h1,  g_h1);
    cudaGetSymbolAddress((void**)&p_z2c, g_z2c);
    cudaGetSymbolAddress((void**)&p_p1,  g_p1);
    cudaGetSymbolAddress((void**)&p_z3c, g_z3c);
    cudaGetSymbolAddress((void**)&p_p2,  g_p2);

    // conv1: CIN=1,  GO=2, WOT=4, HOT=4, TV=2 -> block (56,4)=224 thr
    auto c1 = k_conv<1,16,32,32,2,4,4,2>;
    // conv2: CIN=16, GO=4, WOT=6, HOT=4, TV=2 -> block (32,4)=128 thr
    auto c2 = k_conv<16,32,28,28,4,6,4,2>;
    // conv3: CIN=32, GO=4, WOT=4, HOT=8, TV=4 -> block (16,8)=128 thr
    auto c3 = k_conv<32,32,12,12,4,4,8,4>;
    cudaFuncSetAttribute(c2, cudaFuncAttributeMaxDynamicSharedMemorySize, 32*16*25*4);
    cudaFuncSetAttribute(c3, cudaFuncAttributeMaxDynamicSharedMemorySize, 32*32*25*4);

    k_transpose_x<<<(N_*1024 + 255)/256, 256>>>(x);
    k_transpose_wf1<<<(128*512 + 255)/256, 256>>>(Wf1);

    constexpr int SZ1 = N_*16*28*28;

    c1<<<dim3(7*(T_/2), N_), dim3(56, 4), 16*1*25*4>>>(p_xt, Wc1, bc1, p_z1c);
    k_scan<SZ1><<<(SZ1 + 255)/256, 256>>>(p_z1c, p_h1);

    c2<<<dim3(6*(T_/2), N_), dim3(32, 4), 32*16*25*4>>>(p_h1, Wc2, bc2, p_z2c);
    k_scanpool<32,24><<<(N_*32*12*12 + 255)/256, 256>>>(p_z2c, p_p1);

    c3<<<dim3(1*(T_/4), N_), dim3(16, 8), 32*32*25*4>>>(p_p1, Wc3, bc3, p_z3c);
    k_scanpool<32,8><<<(N_*32*4*4 + 255)/256, 256>>>(p_z3c, p_p2);

    k_fc1<<<dim3(T_/4, N_), 128>>>(bf1);
    k_head<<<N_, 128>>>(Wf2, bf2, out);
}

// round 5
// speedup vs baseline: 2.1727x; 1.1096x over previous
#include <cuda_runtime.h>

#define N_ 32
#define T_ 48

// ---------------- scratch (t-major: [T][N][C][H][W]) ----------------
__device__ float g_xt[(size_t)T_*N_*32*32];          // x transposed (C=1)
__device__ float g_z1c[(size_t)T_*N_*16*28*28];      // conv1 pre-acts
__device__ float g_h1[(size_t)T_*N_*16*28*28];       // conv1 spikes
__device__ float g_z2c[(size_t)T_*N_*32*24*24];      // conv2 pre-acts
__device__ float g_p1[(size_t)T_*N_*32*12*12];       // pool1 spikes
__device__ float g_z3c[(size_t)T_*N_*32*8*8];        // conv3 pre-acts
__device__ float g_p2[(size_t)T_*N_*32*4*4];         // pool2 spikes
__device__ float g_wt1[512*128];                     // Wf1 transposed [k][o]
__device__ float g_z1[(size_t)T_*N_*128];            // fc1 pre-activations

// ---------------- transpose x: [N,1,32,32,T] -> [T][N][32][32] ----------------
__global__ void k_transpose_x(const float* __restrict__ x) {
    int idx = blockIdx.x * blockDim.x + threadIdx.x;
    if (idx >= N_*32*32) return;
    int n = idx >> 10, hw = idx & 1023;
    const float* xp = x + (size_t)idx * T_;
    #pragma unroll
    for (int t = 0; t < T_; t++)
        g_xt[((size_t)t*N_ + n)*1024 + hw] = xp[t];
}

// ---------------- transpose Wf1: [128][512] -> [512][128] ----------------
__global__ void k_transpose_wf1(const float* __restrict__ Wf1) {
    int idx = blockIdx.x * blockDim.x + threadIdx.x;
    if (idx >= 128*512) return;
    int o = idx >> 9, k = idx & 511;
    g_wt1[k*128 + o] = Wf1[idx];
}

// ---------------- 5x5 VALID conv (pre-activation only; parallel over T) ----------------
// Smem weights channel-last: ws[(c*25+k)*COUT + oc] -> LDS.128 per GO=4 group.
// Software-pipelined: double-buffered input rows across the flattened (c,kh) loop.
template<int CIN,int COUT,int HIN,int WIN,int GO,int WOT,int HOT,int TV,int MINB>
__global__ void
__launch_bounds__(((WIN-4)/WOT)*(COUT/GO)*HOT, MINB)
k_conv(const float* __restrict__ in,
       const float* __restrict__ Wc,
       const float* __restrict__ bc,
       float* __restrict__ z) {
    constexpr int HOUT = HIN-4, WOUT = WIN-4;
    constexpr int NWG  = WOUT/WOT;
    constexpr int NOG  = COUT/GO;
    constexpr int LANES = NWG*NOG;
    constexpr int HBLK = HOUT/HOT;
    constexpr int M    = CIN*5;            // flattened (c,kh)
    constexpr size_t TS_IN  = (size_t)N_*CIN*HIN*WIN;
    constexpr size_t TS_OUT = (size_t)N_*COUT*HOUT*WOUT;
    extern __shared__ float ws[];          // CIN*25*COUT, channel-last
    {
        int tid = threadIdx.y*LANES + threadIdx.x;
        for (int i = tid; i < COUT*CIN*25; i += LANES*HOT) {
            int oc = i % COUT;
            int ck = i / COUT;
            ws[i] = Wc[oc*CIN*25 + ck];
        }
    }
    __syncthreads();

    int hb = blockIdx.x % HBLK;
    int t0 = (blockIdx.x / HBLK) * TV;
    int n  = blockIdx.y;
    int wg = threadIdx.x % NWG;
    int og = threadIdx.x / NWG;
    int wo = wg * WOT;
    int ho = hb*HOT + threadIdx.y;

    float acc[GO][WOT][TV];
    #pragma unroll
    for (int g = 0; g < GO; g++) {
        float b = bc[og*GO + g];
        #pragma unroll
        for (int ww = 0; ww < WOT; ww++)
            #pragma unroll
            for (int tv = 0; tv < TV; tv++) acc[g][ww][tv] = b;
    }

    const float* inb = in + (size_t)t0*TS_IN + (size_t)n*CIN*HIN*WIN
                          + (size_t)ho*WIN + wo;

    float va[WOT+4][TV], vb[WOT+4][TV];

    auto load_v = [&](int m, float (&v)[WOT+4][TV]) {
        int c = m / 5, kh = m % 5;
        const float* ip = inb + ((size_t)c*HIN + kh)*WIN;
        #pragma unroll
        for (int tv = 0; tv < TV; tv++) {
            const float2* p2 = reinterpret_cast<const float2*>(ip + (size_t)tv*TS_IN);
            #pragma unroll
            for (int j2 = 0; j2 < (WOT+4)/2; j2++) {
                float2 d = p2[j2];
                v[2*j2][tv]   = d.x;
                v[2*j2+1][tv] = d.y;
            }
        }
    };

    auto fma_step = [&](int m, float (&v)[WOT+4][TV]) {
        #pragma unroll
        for (int kw = 0; kw < 5; kw++) {
            float wreg[GO];
            if constexpr (GO == 4) {
                float4 w4 = *reinterpret_cast<const float4*>(&ws[(m*5 + kw)*COUT + og*4]);
                wreg[0] = w4.x; wreg[1] = w4.y; wreg[2] = w4.z; wreg[3] = w4.w;
            } else if constexpr (GO == 2) {
                float2 w2 = *reinterpret_cast<const float2*>(&ws[(m*5 + kw)*COUT + og*2]);
                wreg[0] = w2.x; wreg[1] = w2.y;
            } else {
                #pragma unroll
                for (int g = 0; g < GO; g++) wreg[g] = ws[(m*5 + kw)*COUT + og*GO + g];
            }
            #pragma unroll
            for (int g = 0; g < GO; g++)
                #pragma unroll
                for (int ww = 0; ww < WOT; ww++)
                    #pragma unroll
                    for (int tv = 0; tv < TV; tv++)
                        acc[g][ww][tv] += v[ww+kw][tv] * wreg[g];
        }
    };

    load_v(0, va);
    int m = 0;
    #pragma unroll 1
    for (; m + 2 <= M; m += 2) {
        load_v(m + 1, vb);
        fma_step(m, va);
        if (m + 2 < M) load_v(m + 2, va);
        fma_step(m + 1, vb);
    }
    if (m < M) fma_step(m, va);   // odd M tail (va preloaded)

    float* zb = z + (size_t)t0*TS_OUT + (size_t)n*COUT*HOUT*WOUT
                  + (size_t)og*GO*HOUT*WOUT + (size_t)ho*WOUT + wo;
    #pragma unroll
    for (int tv = 0; tv < TV; tv++)
        #pragma unroll
        for (int g = 0; g < GO; g++) {
            float* op = zb + (size_t)tv*TS_OUT + (size_t)g*HOUT*WOUT;
            #pragma unroll
            for (int j2 = 0; j2 < WOT/2; j2++) {
                float2 d; d.x = acc[g][2*j2][tv]; d.y = acc[g][2*j2+1][tv];
                reinterpret_cast<float2*>(op)[j2] = d;
            }
        }
}

// ---------------- LIF scan over T: z -> spikes ----------------
template<int SZ>
__global__ void k_scan(const float* __restrict__ z, float* __restrict__ s_out) {
    int idx = blockIdx.x * blockDim.x + threadIdx.x;
    if (idx >= SZ) return;
    float u = 0.f;
    #pragma unroll 4
    for (int t = 0; t < T_; t++) {
        u += z[(size_t)t*SZ + idx];
        float s = (u >= 1.0f) ? 1.0f : 0.0f;
        u -= s;
        s_out[(size_t)t*SZ + idx] = s;
    }
}

// ---------------- fused LIF scan + 2x2 avg-pool + LIF scan ----------------
template<int C,int HIN>
__global__ void k_scanpool(const float* __restrict__ z, float* __restrict__ out) {
    constexpr int HO = HIN/2;
    constexpr size_t TS_IN  = (size_t)N_*C*HIN*HIN;
    constexpr size_t TS_OUT = (size_t)N_*C*HO*HO;
    int idx = blockIdx.x * blockDim.x + threadIdx.x;
    if (idx >= N_*C*HO*HO) return;
    int wo = idx % HO; int t1 = idx / HO;
    int ho = t1 % HO;  int t2 = t1 / HO;
    int c  = t2 % C;   int n  = t2 / C;
    const float* ip = z + ((size_t)n*C + c)*HIN*HIN + (size_t)(2*ho)*HIN + 2*wo;
    float* op = out + ((size_t)n*C + c)*HO*HO + (size_t)ho*HO + wo;
    float u0 = 0.f, u1 = 0.f, u2 = 0.f, u3 = 0.f, up = 0.f;
    #pragma unroll 4
    for (int t = 0; t < T_; t++) {
        const float* p = ip + (size_t)t*TS_IN;
        float2 r0 = *reinterpret_cast<const float2*>(p);
        float2 r1 = *reinterpret_cast<const float2*>(p + HIN);
        u0 += r0.x; float s0 = (u0 >= 1.0f) ? 1.0f : 0.0f; u0 -= s0;
        u1 += r0.y; float s1 = (u1 >= 1.0f) ? 1.0f : 0.0f; u1 -= s1;
        u2 += r1.x; float s2 = (u2 >= 1.0f) ? 1.0f : 0.0f; u2 -= s2;
        u3 += r1.y; float s3 = (u3 >= 1.0f) ? 1.0f : 0.0f; u3 -= s3;
        up += 0.25f*(s0 + s1 + s2 + s3);
        float sp = (up >= 1.0f) ? 1.0f : 0.0f; up -= sp;
        op[(size_t)t*TS_OUT] = sp;
    }
}

// ---------------- fc1 GEMM ----------------
__global__ void k_fc1(const float* __restrict__ bf1) {
    __shared__ float sin_[4][512];
    int t0 = blockIdx.x*4, n = blockIdx.y, o = threadIdx.x;
    for (int i = o; i < 4*512; i += 128) {
        int tv = i >> 9, k = i & 511;
        sin_[tv][k] = g_p2[((size_t)(t0+tv)*N_ + n)*512 + k];
    }
    __syncthreads();
    float b = bf1[o];
    float acc[4] = {b, b, b, b};
    #pragma unroll 4
    for (int k = 0; k < 512; k++) {
        float w = g_wt1[k*128 + o];
        #pragma unroll
        for (int tv = 0; tv < 4; tv++) acc[tv] += sin_[tv][k] * w;
    }
    #pragma unroll
    for (int tv = 0; tv < 4; tv++)
        g_z1[((size_t)(t0+tv)*N_ + n)*128 + o] = acc[tv];
}

// ---------------- head ----------------
__global__ void k_head(const float* __restrict__ Wf2, const float* __restrict__ bf2,
                       float* __restrict__ out) {
    int n = blockIdx.x, o = threadIdx.x;
    __shared__ float s1[128];
    __shared__ float w2[2][128];
    w2[0][o] = Wf2[o];
    w2[1][o] = Wf2[128 + o];
    float u1 = 0.f, u2 = 0.f, ssum = 0.f;
    float b2 = (o < 2) ? bf2[o] : 0.f;
    __syncthreads();
    for (int t = 0; t < T_; t++) {
        float z = g_z1[((size_t)t*N_ + n)*128 + o];
        u1 += z;
        float s = (u1 >= 1.0f) ? 1.0f : 0.0f;
        u1 -= s;
        s1[o] = s;
        __syncthreads();
        if (o < 2) {
            float d = b2;
            #pragma unroll 8
            for (int k = 0; k < 128; k++) d += s1[k] * w2[o][k];
            u2 += d;
            float s2 = (u2 >= 1.0f) ? 1.0f : 0.0f;
            u2 -= s2;
            ssum += s2;
        }
        __syncthreads();
    }
    if (o < 2) out[n*2 + o] = ssum * (1.0f / T_);
}

// ---------------- launch ----------------
extern "C" void kernel_launch(void* const* d_in, const int* in_sizes, int n_in,
                              void* d_out, int out_size) {
    (void)in_sizes; (void)n_in; (void)out_size;
    const float* x   = (const float*)d_in[0];
    const float* Wc1 = (const float*)d_in[1];
    const float* bc1 = (const float*)d_in[2];
    const float* Wc2 = (const float*)d_in[3];
    const float* bc2 = (const float*)d_in[4];
    const float* Wc3 = (const float*)d_in[5];
    const float* bc3 = (const float*)d_in[6];
    const float* Wf1 = (const float*)d_in[7];
    const float* bf1 = (const float*)d_in[8];
    const float* Wf2 = (const float*)d_in[9];
    const float* bf2 = (const float*)d_in[10];
    float* out = (float*)d_out;

    float *p_xt, *p_z1c, *p_h1, *p_z2c, *p_p1, *p_z3c, *p_p2;
    cudaGetSymbolAddress((void**)&p_xt,  g_xt);
    cudaGetSymbolAddress((void**)&p_z1c, g_z1c);
    cudaGetSymbolAddress((void**)&p_h1,  g_h1);
    cudaGetSymbolAddress((void**)&p_z2c, g_z2c);
    cudaGetSymbolAddress((void**)&p_p1,  g_p1);
    cudaGetSymbolAddress((void**)&p_z3c, g_z3c);
    cudaGetSymbolAddress((void**)&p_p2,  g_p2);

    // conv1: CIN=1,  GO=2, WOT=4, HOT=4, TV=2 -> block (56,4)=224 thr
    auto c1 = k_conv<1,16,32,32,2,4,4,2,2>;
    // conv2: CIN=16, GO=4, WOT=6, HOT=4, TV=2 -> block (32,4)=128 thr
    auto c2 = k_conv<16,32,28,28,4,6,4,2,4>;
    // conv3: CIN=32, GO=4, WOT=4, HOT=8, TV=2 -> block (16,8)=128 thr
    auto c3 = k_conv<32,32,12,12,4,4,8,2,4>;
    cudaFuncSetAttribute(c2, cudaFuncAttributeMaxDynamicSharedMemorySize, 32*16*25*4);
    cudaFuncSetAttribute(c3, cudaFuncAttributeMaxDynamicSharedMemorySize, 32*32*25*4);

    k_transpose_x<<<(N_*1024 + 255)/256, 256>>>(x);
    k_transpose_wf1<<<(128*512 + 255)/256, 256>>>(Wf1);

    constexpr int SZ1 = N_*16*28*28;

    c1<<<dim3(7*(T_/2), N_), dim3(56, 4), 16*1*25*4>>>(p_xt, Wc1, bc1, p_z1c);
    k_scan<SZ1><<<(SZ1 + 255)/256, 256>>>(p_z1c, p_h1);

    c2<<<dim3(6*(T_/2), N_), dim3(32, 4), 32*16*25*4>>>(p_h1, Wc2, bc2, p_z2c);
    k_scanpool<32,24><<<(N_*32*12*12 + 255)/256, 256>>>(p_z2c, p_p1);

    c3<<<dim3(1*(T_/2), N_), dim3(16, 8), 32*32*25*4>>>(p_p1, Wc3, bc3, p_z3c);
    k_scanpool<32,8><<<(N_*32*4*4 + 255)/256, 256>>>(p_z3c, p_p2);

    k_fc1<<<dim3(T_/4, N_), 128>>>(bf1);
    k_head<<<N_, 128>>>(Wf2, bf2, out);
}